// round 15
// baseline (speedup 1.0000x reference)
#include <cuda_runtime.h>
#include <cuda_bf16.h>
#include <cuda_fp16.h>
#include <math.h>
#include <stdint.h>

// Problem constants
#define BB 4
#define TT 2048
#define CC 1024
#define HH 16
#define HD 64
#define MROWS (BB * TT)          // 8192
#define N_QKV (3 * CC)           // 3072

// ---------------------------------------------------------------------------
// Global scratch (allocation-free)
// ---------------------------------------------------------------------------
__device__ __half g_xf[MROWS * CC];                                  // x fp16 single
__device__ __half g_wqf[N_QKV * CC], g_wql[N_QKV * CC];              // w_qkv fp16 hi/lo
__device__ __half g_wpf[CC * CC],    g_wpl[CC * CC];                 // w_proj fp16 hi/lo
__device__ __half g_qf[BB * HH * TT * HD];                           // [bh][t][d] fp16
__device__ __half g_kf[BB * HH * TT * HD];                           // [bh][t][d] fp16
__device__ __half g_vf[BB * HH * TT * HD], g_vl[BB * HH * TT * HD];  // [bh][d][t] fp16 hi/lo
__device__ __half g_af[MROWS * CC];                                  // att out [B,T,C] fp16

// ---------------------------------------------------------------------------
// Helpers
// ---------------------------------------------------------------------------
__device__ __forceinline__ uint32_t h2u(__half2 h) {
    return *reinterpret_cast<uint32_t*>(&h);
}
__device__ __forceinline__ uint32_t smem_u32(const void* p) {
    uint32_t a;
    asm("{ .reg .u64 t; cvta.to.shared.u64 t, %1; cvt.u32.u64 %0, t; }"
        : "=r"(a) : "l"(p));
    return a;
}
__device__ __forceinline__ void cpa16(uint32_t dst, const void* src) {
    asm volatile("cp.async.cg.shared.global [%0], [%1], 16;"
                 :: "r"(dst), "l"(src) : "memory");
}
#define CP_COMMIT() asm volatile("cp.async.commit_group;" ::: "memory")
#define CP_WAIT0()  asm volatile("cp.async.wait_group 0;" ::: "memory")
#define CP_WAIT1()  asm volatile("cp.async.wait_group 1;" ::: "memory")

#define LDSM4(r, addr) \
    asm volatile("ldmatrix.sync.aligned.m8n8.x4.shared.b16 {%0,%1,%2,%3}, [%4];" \
        : "=r"((r)[0]), "=r"((r)[1]), "=r"((r)[2]), "=r"((r)[3]) : "r"(addr))

__device__ __forceinline__ float ex2f(float x) {
    float r;
    asm("ex2.approx.f32 %0, %1;" : "=f"(r) : "f"(x));
    return r;
}

__device__ __forceinline__ void mma16816h(float* c, const uint32_t* a,
                                          uint32_t b0, uint32_t b1) {
    asm volatile(
        "mma.sync.aligned.m16n8k16.row.col.f32.f16.f16.f32 "
        "{%0,%1,%2,%3}, {%4,%5,%6,%7}, {%8,%9}, {%0,%1,%2,%3};"
        : "+f"(c[0]), "+f"(c[1]), "+f"(c[2]), "+f"(c[3])
        : "r"(a[0]), "r"(a[1]), "r"(a[2]), "r"(a[3]), "r"(b0), "r"(b1));
}

// ---------------------------------------------------------------------------
// Elementwise pre-passes
// ---------------------------------------------------------------------------
__global__ void tofp16_kernel(const float* __restrict__ src,
                              __half* __restrict__ d, int n4) {
    int i = blockIdx.x * blockDim.x + threadIdx.x;
    int stride = gridDim.x * blockDim.x;
    for (; i < n4; i += stride) {
        float4 v = ((const float4*)src)[i];
        ((uint2*)d)[i] = make_uint2(h2u(__floats2half2_rn(v.x, v.y)),
                                    h2u(__floats2half2_rn(v.z, v.w)));
    }
}

__global__ void split_kernel_h(const float* __restrict__ src,
                               __half* __restrict__ dh,
                               __half* __restrict__ dl, int n4) {
    int i = blockIdx.x * blockDim.x + threadIdx.x;
    int stride = gridDim.x * blockDim.x;
    for (; i < n4; i += stride) {
        float4 v = ((const float4*)src)[i];
        __half2 h01 = __floats2half2_rn(v.x, v.y);
        __half2 h23 = __floats2half2_rn(v.z, v.w);
        float2 f01 = __half22float2(h01);
        float2 f23 = __half22float2(h23);
        __half2 l01 = __floats2half2_rn(v.x - f01.x, v.y - f01.y);
        __half2 l23 = __floats2half2_rn(v.z - f23.x, v.w - f23.y);
        ((uint2*)dh)[i] = make_uint2(h2u(h01), h2u(h23));
        ((uint2*)dl)[i] = make_uint2(h2u(l01), h2u(l23));
    }
}

// ---------------------------------------------------------------------------
// 2-product fp16 NT GEMM skeleton (A fp16 single, B fp16 hi/lo):
// 3-stage cp.async pipeline, ONE barrier per chunk, ldmatrix, 2 CTAs/SM.
// 128x128 tile, K-chunk 32, 8 warps 4x2, smem rows padded to 80B
// (identical LDSM-conflict-free layout as the verified 2-stage version).
// qkv_gemm: epilogue writes Q/K fp16 + V fp16 hi/lo transposed.
// proj_gemm: epilogue writes out = C + bias (fp32).
// ---------------------------------------------------------------------------
#define APAD_B 80
#define TILE_B (128 * APAD_B)              // 10240
#define PBUF_B (3 * TILE_B)                // AF, BH, BL = 30720
#define NSTAGE 3
#define GSMEM  (NSTAGE * PBUF_B)           // 92160 (covers Ds 67584 too)
#define NCHUNK (CC / 32)                   // 32

// Shared mainloop body (identical for both GEMMs)
#define GEMM_MAINLOOP(AF, BH, BL)                                              \
    const uint32_t smb = smem_u32(smc);                                        \
    const int tid = threadIdx.x;                                               \
    const int m0 = blockIdx.y * 128;                                           \
    const int n0 = blockIdx.x * 128;                                           \
    const int wid = tid >> 5;                                                  \
    const int lane = tid & 31;                                                 \
    const int gid = lane >> 2;                                                 \
    const int tig = lane & 3;                                                  \
    const int wm = wid & 3;                                                    \
    const int wn = wid >> 2;                                                   \
    const uint32_t laneA = (uint32_t)(((lane & 7) + ((lane >> 3) & 1) * 8)     \
                                      * APAD_B + (lane >> 4) * 16);            \
    const uint32_t laneB = (uint32_t)(((lane & 7) + ((lane >> 4) & 1) * 8)     \
                                      * APAD_B + ((lane >> 3) & 1) * 16);      \
    float acc[2][8][4];                                                        \
    _Pragma("unroll")                                                          \
    for (int i = 0; i < 2; i++)                                                \
        _Pragma("unroll")                                                      \
        for (int j = 0; j < 8; j++)                                            \
            _Pragma("unroll")                                                  \
            for (int q = 0; q < 4; q++) acc[i][j][q] = 0.f;                    \
    auto copyc = [&](int kk, int bufi) {                                       \
        uint32_t bbase = smb + bufi * PBUF_B;                                  \
        _Pragma("unroll")                                                      \
        for (int l = 0; l < 6; l++) {                                          \
            const int tile = l >> 1;                                           \
            int e2 = (l & 1) * 256 + tid;                                      \
            int r = e2 >> 2;                                                   \
            int q = e2 & 3;                                                    \
            const __half* src = (tile == 0) ? AF : (tile == 1) ? BH : BL;      \
            int row = (tile == 0 ? m0 : n0) + r;                               \
            cpa16(bbase + tile * TILE_B + r * APAD_B + q * 16,                 \
                  src + (size_t)row * CC + kk + q * 8);                        \
        }                                                                      \
    };                                                                         \
    auto compute = [&](uint32_t bufu) {                                        \
        _Pragma("unroll")                                                      \
        for (int ks = 0; ks < 2; ks++) {                                       \
            uint32_t af[2][4];                                                 \
            _Pragma("unroll")                                                  \
            for (int i = 0; i < 2; i++) {                                      \
                uint32_t aaddr = bufu + laneA + (wm * 32 + i * 16) * APAD_B    \
                               + ks * 32;                                      \
                LDSM4(af[i], aaddr);                                           \
            }                                                                  \
            _Pragma("unroll")                                                  \
            for (int jp = 0; jp < 4; jp++) {                                   \
                uint32_t baddr = bufu + TILE_B + laneB                         \
                               + (wn * 64 + jp * 16) * APAD_B + ks * 32;       \
                uint32_t rh[4], rl[4];                                         \
                LDSM4(rh, baddr);                                              \
                LDSM4(rl, baddr + TILE_B);                                     \
                _Pragma("unroll")                                              \
                for (int t = 0; t < 2; t++) {                                  \
                    int j = 2 * jp + t;                                        \
                    _Pragma("unroll")                                          \
                    for (int i = 0; i < 2; i++) {                              \
                        mma16816h(acc[i][j], af[i], rh[2 * t], rh[2 * t + 1]); \
                        mma16816h(acc[i][j], af[i], rl[2 * t], rl[2 * t + 1]); \
                    }                                                          \
                }                                                              \
            }                                                                  \
        }                                                                      \
    };                                                                         \
    /* 3-stage, one barrier per chunk: wait(c) -> bar -> copy(c+2) -> comp(c)*/\
    copyc(0, 0);  CP_COMMIT();                                                 \
    copyc(32, 1); CP_COMMIT();                                                 \
    for (int c = 0; c < NCHUNK; c++) {                                         \
        if (c + 1 < NCHUNK) { CP_WAIT1(); } else { CP_WAIT0(); }               \
        __syncthreads();   /* all threads done with compute(c-1) */            \
        if (c + 2 < NCHUNK) {                                                  \
            copyc((c + 2) * 32, (c + 2) % 3);                                  \
            CP_COMMIT();                                                       \
        }                                                                      \
        compute(smb + (uint32_t)(c % 3) * PBUF_B);                             \
    }                                                                          \
    __syncthreads();                                                           \
    float* Ds = (float*)smc;                                                   \
    _Pragma("unroll")                                                          \
    for (int i = 0; i < 2; i++) {                                              \
        int rr = wm * 32 + i * 16 + gid;                                       \
        _Pragma("unroll")                                                      \
        for (int j = 0; j < 8; j++) {                                          \
            int cc = wn * 64 + j * 8 + tig * 2;                                \
            *(float2*)&Ds[rr * 132 + cc] =                                     \
                make_float2(acc[i][j][0], acc[i][j][1]);                       \
            *(float2*)&Ds[(rr + 8) * 132 + cc] =                               \
                make_float2(acc[i][j][2], acc[i][j][3]);                       \
        }                                                                      \
    }                                                                          \
    __syncthreads();

__global__ __launch_bounds__(256, 2) void qkv_gemm(
    const __half* __restrict__ AF,
    const __half* __restrict__ WH, const __half* __restrict__ WL) {
    extern __shared__ char smc[];
    GEMM_MAINLOOP(AF, WH, WL)

    // two 64-wide segments; each wholly one of q/k/v (192 % 64 == 0)
#pragma unroll
    for (int seg = 0; seg < 2; seg++) {
        int gn0 = n0 + seg * 64;
        int h = gn0 / 192;
        int part = (gn0 % 192) >> 6;
        if (part < 2) {
            __half* dst = (part == 0) ? g_qf : g_kf;       // fp16, single
#pragma unroll
            for (int it = 0; it < 16; it++) {
                int m = it * 8 + (tid >> 5);
                int d2 = (tid & 31) * 2;
                float v0 = Ds[m * 132 + seg * 64 + d2];
                float v1 = Ds[m * 132 + seg * 64 + d2 + 1];
                __half2 hp = __floats2half2_rn(v0, v1);
                int gm = m0 + m; int b = gm >> 11; int t = gm & 2047;
                size_t idx = (((size_t)(b * HH + h)) * TT + t) * HD + d2;
                *(uint32_t*)(dst + idx) = h2u(hp);
            }
        } else {                            // V: transposed [bh][d][t], fp16 hi/lo
#pragma unroll
            for (int it = 0; it < 16; it++) {
                int flat = it * 256 + tid;         // 0..4095
                int d = flat >> 6;                 // 0..63
                int tp = (flat & 63) * 2;          // pair along t
                float v0 = Ds[tp * 132 + seg * 64 + d];
                float v1 = Ds[(tp + 1) * 132 + seg * 64 + d];
                __half2 hp = __floats2half2_rn(v0, v1);
                float2 hf = __half22float2(hp);
                __half2 lp = __floats2half2_rn(v0 - hf.x, v1 - hf.y);
                int gm = m0 + tp; int b = gm >> 11; int t = gm & 2047;
                size_t idx = (((size_t)(b * HH + h)) * HD + d) * TT + t;
                *(uint32_t*)(g_vf + idx) = h2u(hp);
                *(uint32_t*)(g_vl + idx) = h2u(lp);
            }
        }
    }
}

__global__ __launch_bounds__(256, 2) void proj_gemm(
    const __half* __restrict__ AF,
    const __half* __restrict__ WH, const __half* __restrict__ WL,
    const float* __restrict__ bias, float* __restrict__ out) {
    extern __shared__ char smc[];
    GEMM_MAINLOOP(AF, WH, WL)

#pragma unroll 4
    for (int ll = 0; ll < 64; ll++) {
        int flat = ll * 256 + tid;
        int n = flat & 127;
        int m = flat >> 7;
        out[(size_t)(m0 + m) * CC + n0 + n] = Ds[m * 132 + n] + bias[n0 + n];
    }
}

// ---------------------------------------------------------------------------
// Flash attention (unchanged from R13). S = single fp16 MMA; PV = pf*(vh+vl).
// BM=128 (8 warps x 16 rows), BN=64, 2 CTAs/SM, base-2 softmax, heavy-first.
// ---------------------------------------------------------------------------
#define AT_ROW 144
#define AT_TILE (64 * AT_ROW)              // 9216
#define AT_BUF (3 * AT_TILE)               // 27648
#define ATT_SMEM_BYTES (2 * AT_BUF)        // 55296
#define SCL2 0.1803368801111137f           // 0.125 * log2(e)

__global__ __launch_bounds__(256, 2) void attn_kernel() {
    extern __shared__ char smc[];
    const uint32_t smb = smem_u32(smc);
    const int tid = threadIdx.x;
    const int bh = blockIdx.y;
    const int q0 = (gridDim.x - 1 - blockIdx.x) * 128;   // heavy tiles first
    const int wid = tid >> 5;
    const int lane = tid & 31;
    const int gid = lane >> 2;
    const int tig = lane & 3;
    const int r0 = q0 + wid * 16 + gid;

    const __half* Qf = g_qf + (size_t)bh * TT * HD;
    const __half* Kf = g_kf + (size_t)bh * TT * HD;
    const __half* Vf = g_vf + (size_t)bh * HD * TT;
    const __half* Vl = g_vl + (size_t)bh * HD * TT;

    const uint32_t laneB = (uint32_t)(((lane & 7) + ((lane >> 4) & 1) * 8) * AT_ROW
                                      + ((lane >> 3) & 1) * 16);

    // ---- Q fragments (fp16, single), direct ldg
    uint32_t qf[4][4];
#pragma unroll
    for (int ks = 0; ks < 4; ks++)
#pragma unroll
        for (int hv = 0; hv < 2; hv++)
#pragma unroll
            for (int rr = 0; rr < 2; rr++) {
                size_t o = (size_t)(r0 + rr * 8) * HD + ks * 16 + hv * 8 + tig * 2;
                qf[ks][hv * 2 + rr] = *(const uint32_t*)(Qf + o);
            }

    float oacc[8][4];
#pragma unroll
    for (int j = 0; j < 8; j++)
#pragma unroll
        for (int q = 0; q < 4; q++) oacc[j][q] = 0.f;
    float mr0 = -1e30f, mr1 = -1e30f, lr0 = 0.f, lr1 = 0.f;

    auto copyc = [&](int c, int bufi) {
        const int k0 = c * 64;
        uint32_t bbase = smb + bufi * AT_BUF;
#pragma unroll
        for (int l = 0; l < 6; l++) {
            const int tile = l >> 1;            // 0=Kf, 1=Vf, 2=Vl
            int e2 = (l & 1) * 256 + tid;       // 0..511
            int r = e2 >> 3;                    // 0..63
            int q = e2 & 7;                     // 0..7
            const void* src;
            if (tile == 0)      src = Kf + (size_t)(k0 + r) * HD + q * 8;
            else if (tile == 1) src = Vf + (size_t)r * TT + k0 + q * 8;
            else                src = Vl + (size_t)r * TT + k0 + q * 8;
            cpa16(bbase + tile * AT_TILE + r * AT_ROW + q * 16, src);
        }
    };

    const int jmax = (q0 >> 6) + 2;
    copyc(0, 0);
    CP_COMMIT();
    for (int c = 0; c < jmax; c++) {
        if (c + 1 < jmax) {
            copyc(c + 1, (c + 1) & 1);
            CP_COMMIT();
            CP_WAIT1();
        } else {
            CP_WAIT0();
        }
        __syncthreads();
        const uint32_t KT = smb + (uint32_t)(c & 1) * AT_BUF;
        const uint32_t VT = KT + AT_TILE;

        // ---- S = Q K^T, single fp16 product
        float s[8][4];
#pragma unroll
        for (int j = 0; j < 8; j++)
#pragma unroll
            for (int q = 0; q < 4; q++) s[j][q] = 0.f;
#pragma unroll
        for (int ks = 0; ks < 4; ks++) {
#pragma unroll
            for (int jp = 0; jp < 4; jp++) {
                uint32_t kaddr = KT + laneB + jp * 16 * AT_ROW + ks * 32;
                uint32_t rk[4];
                LDSM4(rk, kaddr);
#pragma unroll
                for (int t = 0; t < 2; t++) {
                    int j = 2 * jp + t;
                    mma16816h(s[j], qf[ks], rk[2 * t], rk[2 * t + 1]);
                }
            }
        }

        // scale into base-2 logit domain
        const int k0 = c * 64;
#pragma unroll
        for (int j = 0; j < 8; j++)
#pragma unroll
            for (int q = 0; q < 4; q++) s[j][q] *= SCL2;
        if (c >= jmax - 2) {
#pragma unroll
            for (int j = 0; j < 8; j++) {
                int col = k0 + 8 * j + 2 * tig;
                if (col > r0)          s[j][0] = -1e30f;
                if (col + 1 > r0)      s[j][1] = -1e30f;
                if (col > r0 + 8)      s[j][2] = -1e30f;
                if (col + 1 > r0 + 8)  s[j][3] = -1e30f;
            }
        }

        // ---- online softmax (base-2)
        float pm0 = -1e30f, pm1 = -1e30f;
#pragma unroll
        for (int j = 0; j < 8; j++) {
            pm0 = fmaxf(pm0, fmaxf(s[j][0], s[j][1]));
            pm1 = fmaxf(pm1, fmaxf(s[j][2], s[j][3]));
        }
        pm0 = fmaxf(pm0, __shfl_xor_sync(0xffffffffu, pm0, 1));
        pm0 = fmaxf(pm0, __shfl_xor_sync(0xffffffffu, pm0, 2));
        pm1 = fmaxf(pm1, __shfl_xor_sync(0xffffffffu, pm1, 1));
        pm1 = fmaxf(pm1, __shfl_xor_sync(0xffffffffu, pm1, 2));
        float mn0 = fmaxf(mr0, pm0), mn1 = fmaxf(mr1, pm1);
        float a0 = ex2f(mr0 - mn0), a1 = ex2f(mr1 - mn1);
        float sum0 = 0.f, sum1 = 0.f;
#pragma unroll
        for (int j = 0; j < 8; j++) {
            s[j][0] = ex2f(s[j][0] - mn0);
            s[j][1] = ex2f(s[j][1] - mn0);
            s[j][2] = ex2f(s[j][2] - mn1);
            s[j][3] = ex2f(s[j][3] - mn1);
            sum0 += s[j][0] + s[j][1];
            sum1 += s[j][2] + s[j][3];
        }
        sum0 += __shfl_xor_sync(0xffffffffu, sum0, 1);
        sum0 += __shfl_xor_sync(0xffffffffu, sum0, 2);
        sum1 += __shfl_xor_sync(0xffffffffu, sum1, 1);
        sum1 += __shfl_xor_sync(0xffffffffu, sum1, 2);
        lr0 = lr0 * a0 + sum0;
        lr1 = lr1 * a1 + sum1;
        mr0 = mn0; mr1 = mn1;
#pragma unroll
        for (int j = 0; j < 8; j++) {
            oacc[j][0] *= a0; oacc[j][1] *= a0;
            oacc[j][2] *= a1; oacc[j][3] *= a1;
        }

        // ---- O += P V (pf * vh + pf * vl), P single fp16, packed per-ks
#pragma unroll
        for (int ks = 0; ks < 4; ks++) {
            uint32_t pf[4];
            int j0 = 2 * ks, j1 = 2 * ks + 1;
#pragma unroll
            for (int part = 0; part < 4; part++) {
                int jj = (part < 2) ? j0 : j1;
                int qa = (part & 1) * 2;
                pf[part] = h2u(__floats2half2_rn(s[jj][qa], s[jj][qa + 1]));
            }
#pragma unroll
            for (int jp = 0; jp < 4; jp++) {
                uint32_t vaddr = VT + laneB + jp * 16 * AT_ROW + ks * 32;
                uint32_t rh[4], rl[4];
                LDSM4(rh, vaddr);
                LDSM4(rl, vaddr + AT_TILE);
#pragma unroll
                for (int t = 0; t < 2; t++) {
                    int j = 2 * jp + t;
                    mma16816h(oacc[j], pf, rh[2 * t], rh[2 * t + 1]);
                    mma16816h(oacc[j], pf, rl[2 * t], rl[2 * t + 1]);
                }
            }
        }
        __syncthreads();
    }

    // ---- epilogue: normalize, write g_af (fp16 single) [B,T,C]
    const int b = bh >> 4;
    const int h = bh & 15;
    float inv0 = 1.f / lr0, inv1 = 1.f / lr1;
#pragma unroll
    for (int j = 0; j < 8; j++) {
        int d = 8 * j + 2 * tig;
        size_t o0 = ((size_t)(b * TT + r0)) * CC + h * HD + d;
        size_t o1 = ((size_t)(b * TT + r0 + 8)) * CC + h * HD + d;
        *(uint32_t*)(g_af + o0) =
            h2u(__floats2half2_rn(oacc[j][0] * inv0, oacc[j][1] * inv0));
        *(uint32_t*)(g_af + o1) =
            h2u(__floats2half2_rn(oacc[j][2] * inv1, oacc[j][3] * inv1));
    }
}

// ---------------------------------------------------------------------------

extern "C" void kernel_launch(void* const* d_in, const int* in_sizes, int n_in,
                              void* d_out, int out_size) {
    const float* x      = (const float*)d_in[0];
    const float* w_qkv  = (const float*)d_in[1];
    const float* w_proj = (const float*)d_in[2];
    const float* b_proj = (const float*)d_in[3];
    float* out = (float*)d_out;

    __half *xf, *wqf, *wql, *wpf, *wpl, *af;
    cudaGetSymbolAddress((void**)&xf,  g_xf);
    cudaGetSymbolAddress((void**)&wqf, g_wqf);
    cudaGetSymbolAddress((void**)&wql, g_wql);
    cudaGetSymbolAddress((void**)&wpf, g_wpf);
    cudaGetSymbolAddress((void**)&wpl, g_wpl);
    cudaGetSymbolAddress((void**)&af,  g_af);

    cudaFuncSetAttribute(qkv_gemm, cudaFuncAttributeMaxDynamicSharedMemorySize, GSMEM);
    cudaFuncSetAttribute(proj_gemm, cudaFuncAttributeMaxDynamicSharedMemorySize, GSMEM);
    cudaFuncSetAttribute(attn_kernel, cudaFuncAttributeMaxDynamicSharedMemorySize, ATT_SMEM_BYTES);

    tofp16_kernel<<<2048, 256>>>(x, xf, MROWS * CC / 4);
    split_kernel_h<<<2048, 256>>>(w_qkv, wqf, wql, N_QKV * CC / 4);
    split_kernel_h<<<1024, 256>>>(w_proj, wpf, wpl, CC * CC / 4);

    qkv_gemm<<<dim3(N_QKV / 128, MROWS / 128), 256, GSMEM>>>(xf, wqf, wql);
    attn_kernel<<<dim3(TT / 128, BB * HH), 256, ATT_SMEM_BYTES>>>();
    proj_gemm<<<dim3(CC / 128, MROWS / 128), 256, GSMEM>>>(af, wpf, wpl, b_proj, out);
}

// round 16
// speedup vs baseline: 1.2374x; 1.2374x over previous
#include <cuda_runtime.h>
#include <cuda_bf16.h>
#include <cuda_fp16.h>
#include <math.h>
#include <stdint.h>

// Problem constants
#define BB 4
#define TT 2048
#define CC 1024
#define HH 16
#define HD 64
#define MROWS (BB * TT)          // 8192
#define N_QKV (3 * CC)           // 3072

// ---------------------------------------------------------------------------
// Global scratch (allocation-free)
// ---------------------------------------------------------------------------
__device__ __half g_xf[MROWS * CC];                                  // x fp16 single
__device__ __half g_wqf[N_QKV * CC];                                 // w_qkv fp16 single
__device__ __half g_wpf[CC * CC],    g_wpl[CC * CC];                 // w_proj fp16 hi/lo
__device__ __half g_qf[BB * HH * TT * HD];                           // [bh][t][d] fp16
__device__ __half g_kf[BB * HH * TT * HD];                           // [bh][t][d] fp16
__device__ __half g_vf[BB * HH * TT * HD], g_vl[BB * HH * TT * HD];  // [bh][d][t] fp16 hi/lo
__device__ __half g_af[MROWS * CC];                                  // att out [B,T,C] fp16

// ---------------------------------------------------------------------------
// Helpers
// ---------------------------------------------------------------------------
__device__ __forceinline__ uint32_t h2u(__half2 h) {
    return *reinterpret_cast<uint32_t*>(&h);
}
__device__ __forceinline__ uint32_t smem_u32(const void* p) {
    uint32_t a;
    asm("{ .reg .u64 t; cvta.to.shared.u64 t, %1; cvt.u32.u64 %0, t; }"
        : "=r"(a) : "l"(p));
    return a;
}
__device__ __forceinline__ void cpa16(uint32_t dst, const void* src) {
    asm volatile("cp.async.cg.shared.global [%0], [%1], 16;"
                 :: "r"(dst), "l"(src) : "memory");
}
#define CP_COMMIT() asm volatile("cp.async.commit_group;" ::: "memory")
#define CP_WAIT0()  asm volatile("cp.async.wait_group 0;" ::: "memory")
#define CP_WAIT1()  asm volatile("cp.async.wait_group 1;" ::: "memory")

#define LDSM4(r, addr) \
    asm volatile("ldmatrix.sync.aligned.m8n8.x4.shared.b16 {%0,%1,%2,%3}, [%4];" \
        : "=r"((r)[0]), "=r"((r)[1]), "=r"((r)[2]), "=r"((r)[3]) : "r"(addr))

__device__ __forceinline__ float ex2f(float x) {
    float r;
    asm("ex2.approx.f32 %0, %1;" : "=f"(r) : "f"(x));
    return r;
}

__device__ __forceinline__ void mma16816h(float* c, const uint32_t* a,
                                          uint32_t b0, uint32_t b1) {
    asm volatile(
        "mma.sync.aligned.m16n8k16.row.col.f32.f16.f16.f32 "
        "{%0,%1,%2,%3}, {%4,%5,%6,%7}, {%8,%9}, {%0,%1,%2,%3};"
        : "+f"(c[0]), "+f"(c[1]), "+f"(c[2]), "+f"(c[3])
        : "r"(a[0]), "r"(a[1]), "r"(a[2]), "r"(a[3]), "r"(b0), "r"(b1));
}

// ---------------------------------------------------------------------------
// Elementwise pre-passes
// ---------------------------------------------------------------------------
__global__ void tofp16_kernel(const float* __restrict__ src,
                              __half* __restrict__ d, int n4) {
    int i = blockIdx.x * blockDim.x + threadIdx.x;
    int stride = gridDim.x * blockDim.x;
    for (; i < n4; i += stride) {
        float4 v = ((const float4*)src)[i];
        ((uint2*)d)[i] = make_uint2(h2u(__floats2half2_rn(v.x, v.y)),
                                    h2u(__floats2half2_rn(v.z, v.w)));
    }
}

__global__ void split_kernel_h(const float* __restrict__ src,
                               __half* __restrict__ dh,
                               __half* __restrict__ dl, int n4) {
    int i = blockIdx.x * blockDim.x + threadIdx.x;
    int stride = gridDim.x * blockDim.x;
    for (; i < n4; i += stride) {
        float4 v = ((const float4*)src)[i];
        __half2 h01 = __floats2half2_rn(v.x, v.y);
        __half2 h23 = __floats2half2_rn(v.z, v.w);
        float2 f01 = __half22float2(h01);
        float2 f23 = __half22float2(h23);
        __half2 l01 = __floats2half2_rn(v.x - f01.x, v.y - f01.y);
        __half2 l23 = __floats2half2_rn(v.z - f23.x, v.w - f23.y);
        ((uint2*)dh)[i] = make_uint2(h2u(h01), h2u(h23));
        ((uint2*)dl)[i] = make_uint2(h2u(l01), h2u(l23));
    }
}

// ---------------------------------------------------------------------------
// Common GEMM geometry: 128x128 tile, K-chunk 32, 8 warps 4x2,
// smem rows padded to 80B (LDSM conflict-free), cp.async double-buffer,
// 2 CTAs/SM (R13-verified pipeline: 2 stages, 2 barriers/chunk).
// ---------------------------------------------------------------------------
#define APAD_B 80
#define TILE_B (128 * APAD_B)              // 10240
#define QBUF_B (2 * TILE_B)                // AF, WF = 20480 (qkv, 1 product)
#define PBUF_B (3 * TILE_B)                // AF, WH, WL = 30720 (proj, 2 products)
#define GSMEM  (128 * 132 * 4)             // 67584: covers both pipelines + Ds
#define NCHUNK (CC / 32)                   // 32

#define GEMM_PREAMBLE                                                          \
    const uint32_t smb = smem_u32(smc);                                        \
    const int tid = threadIdx.x;                                               \
    const int m0 = blockIdx.y * 128;                                           \
    const int n0 = blockIdx.x * 128;                                           \
    const int wid = tid >> 5;                                                  \
    const int lane = tid & 31;                                                 \
    const int gid = lane >> 2;                                                 \
    const int tig = lane & 3;                                                  \
    const int wm = wid & 3;                                                    \
    const int wn = wid >> 2;                                                   \
    const uint32_t laneA = (uint32_t)(((lane & 7) + ((lane >> 3) & 1) * 8)     \
                                      * APAD_B + (lane >> 4) * 16);            \
    const uint32_t laneB = (uint32_t)(((lane & 7) + ((lane >> 4) & 1) * 8)     \
                                      * APAD_B + ((lane >> 3) & 1) * 16);      \
    float acc[2][8][4];                                                        \
    _Pragma("unroll")                                                          \
    for (int i = 0; i < 2; i++)                                                \
        _Pragma("unroll")                                                      \
        for (int j = 0; j < 8; j++)                                            \
            _Pragma("unroll")                                                  \
            for (int q = 0; q < 4; q++) acc[i][j][q] = 0.f;

#define GEMM_EPI_STAGE                                                         \
    float* Ds = (float*)smc;                                                   \
    _Pragma("unroll")                                                          \
    for (int i = 0; i < 2; i++) {                                              \
        int rr = wm * 32 + i * 16 + gid;                                       \
        _Pragma("unroll")                                                      \
        for (int j = 0; j < 8; j++) {                                          \
            int cc = wn * 64 + j * 8 + tig * 2;                                \
            *(float2*)&Ds[rr * 132 + cc] =                                     \
                make_float2(acc[i][j][0], acc[i][j][1]);                       \
            *(float2*)&Ds[(rr + 8) * 132 + cc] =                               \
                make_float2(acc[i][j][2], acc[i][j][3]);                       \
        }                                                                      \
    }                                                                          \
    __syncthreads();

// ---------------------------------------------------------------------------
// QKV GEMM: single fp16 product (A fp16, W fp16). Epilogue writes
// Q/K fp16 + V fp16 hi/lo transposed.
// ---------------------------------------------------------------------------
__global__ __launch_bounds__(256, 2) void qkv_gemm(
    const __half* __restrict__ AF, const __half* __restrict__ WF) {
    extern __shared__ char smc[];
    GEMM_PREAMBLE

    auto copyc = [&](int kk, int bufi) {
        uint32_t bbase = smb + bufi * QBUF_B;
#pragma unroll
        for (int l = 0; l < 4; l++) {
            const int tile = l >> 1;               // 0=AF, 1=WF
            int e2 = (l & 1) * 256 + tid;          // 0..511
            int r = e2 >> 2;
            int q = e2 & 3;
            const __half* src = (tile == 0) ? AF : WF;
            int row = (tile == 0 ? m0 : n0) + r;
            cpa16(bbase + tile * TILE_B + r * APAD_B + q * 16,
                  src + (size_t)row * CC + kk + q * 8);
        }
    };

    auto compute = [&](uint32_t bufu) {
#pragma unroll
        for (int ks = 0; ks < 2; ks++) {
            uint32_t af[2][4];
#pragma unroll
            for (int i = 0; i < 2; i++) {
                uint32_t aaddr = bufu + laneA + (wm * 32 + i * 16) * APAD_B + ks * 32;
                LDSM4(af[i], aaddr);
            }
#pragma unroll
            for (int jp = 0; jp < 4; jp++) {
                uint32_t baddr = bufu + TILE_B + laneB
                               + (wn * 64 + jp * 16) * APAD_B + ks * 32;
                uint32_t rf[4];
                LDSM4(rf, baddr);
#pragma unroll
                for (int t = 0; t < 2; t++) {
                    int j = 2 * jp + t;
#pragma unroll
                    for (int i = 0; i < 2; i++)
                        mma16816h(acc[i][j], af[i], rf[2 * t], rf[2 * t + 1]);
                }
            }
        }
    };

    copyc(0, 0);
    CP_COMMIT();
    for (int c = 0; c < NCHUNK; c++) {
        if (c + 1 < NCHUNK) {
            copyc((c + 1) * 32, (c + 1) & 1);
            CP_COMMIT();
            CP_WAIT1();
        } else {
            CP_WAIT0();
        }
        __syncthreads();
        compute(smb + (uint32_t)(c & 1) * QBUF_B);
        __syncthreads();
    }

    GEMM_EPI_STAGE

    // two 64-wide segments; each wholly one of q/k/v (192 % 64 == 0)
#pragma unroll
    for (int seg = 0; seg < 2; seg++) {
        int gn0 = n0 + seg * 64;
        int h = gn0 / 192;
        int part = (gn0 % 192) >> 6;
        if (part < 2) {
            __half* dst = (part == 0) ? g_qf : g_kf;       // fp16, single
#pragma unroll
            for (int it = 0; it < 16; it++) {
                int m = it * 8 + (tid >> 5);
                int d2 = (tid & 31) * 2;
                float v0 = Ds[m * 132 + seg * 64 + d2];
                float v1 = Ds[m * 132 + seg * 64 + d2 + 1];
                __half2 hp = __floats2half2_rn(v0, v1);
                int gm = m0 + m; int b = gm >> 11; int t = gm & 2047;
                size_t idx = (((size_t)(b * HH + h)) * TT + t) * HD + d2;
                *(uint32_t*)(dst + idx) = h2u(hp);
            }
        } else {                            // V: transposed [bh][d][t], fp16 hi/lo
#pragma unroll
            for (int it = 0; it < 16; it++) {
                int flat = it * 256 + tid;         // 0..4095
                int d = flat >> 6;                 // 0..63
                int tp = (flat & 63) * 2;          // pair along t
                float v0 = Ds[tp * 132 + seg * 64 + d];
                float v1 = Ds[(tp + 1) * 132 + seg * 64 + d];
                __half2 hp = __floats2half2_rn(v0, v1);
                float2 hf = __half22float2(hp);
                __half2 lp = __floats2half2_rn(v0 - hf.x, v1 - hf.y);
                int gm = m0 + tp; int b = gm >> 11; int t = gm & 2047;
                size_t idx = (((size_t)(b * HH + h)) * HD + d) * TT + t;
                *(uint32_t*)(g_vf + idx) = h2u(hp);
                *(uint32_t*)(g_vl + idx) = h2u(lp);
            }
        }
    }
}

// ---------------------------------------------------------------------------
// Proj GEMM: 2 fp16 products (A fp16 single, W fp16 hi/lo). out = C + bias.
// ---------------------------------------------------------------------------
__global__ __launch_bounds__(256, 2) void proj_gemm(
    const __half* __restrict__ AF,
    const __half* __restrict__ WH, const __half* __restrict__ WL,
    const float* __restrict__ bias, float* __restrict__ out) {
    extern __shared__ char smc[];
    GEMM_PREAMBLE

    auto copyc = [&](int kk, int bufi) {
        uint32_t bbase = smb + bufi * PBUF_B;
#pragma unroll
        for (int l = 0; l < 6; l++) {
            const int tile = l >> 1;               // 0=AF, 1=WH, 2=WL
            int e2 = (l & 1) * 256 + tid;
            int r = e2 >> 2;
            int q = e2 & 3;
            const __half* src = (tile == 0) ? AF : (tile == 1) ? WH : WL;
            int row = (tile == 0 ? m0 : n0) + r;
            cpa16(bbase + tile * TILE_B + r * APAD_B + q * 16,
                  src + (size_t)row * CC + kk + q * 8);
        }
    };

    auto compute = [&](uint32_t bufu) {
#pragma unroll
        for (int ks = 0; ks < 2; ks++) {
            uint32_t af[2][4];
#pragma unroll
            for (int i = 0; i < 2; i++) {
                uint32_t aaddr = bufu + laneA + (wm * 32 + i * 16) * APAD_B + ks * 32;
                LDSM4(af[i], aaddr);
            }
#pragma unroll
            for (int jp = 0; jp < 4; jp++) {
                uint32_t baddr = bufu + TILE_B + laneB
                               + (wn * 64 + jp * 16) * APAD_B + ks * 32;
                uint32_t rh[4], rl[4];
                LDSM4(rh, baddr);
                LDSM4(rl, baddr + TILE_B);
#pragma unroll
                for (int t = 0; t < 2; t++) {
                    int j = 2 * jp + t;
#pragma unroll
                    for (int i = 0; i < 2; i++) {
                        mma16816h(acc[i][j], af[i], rh[2 * t], rh[2 * t + 1]);
                        mma16816h(acc[i][j], af[i], rl[2 * t], rl[2 * t + 1]);
                    }
                }
            }
        }
    };

    copyc(0, 0);
    CP_COMMIT();
    for (int c = 0; c < NCHUNK; c++) {
        if (c + 1 < NCHUNK) {
            copyc((c + 1) * 32, (c + 1) & 1);
            CP_COMMIT();
            CP_WAIT1();
        } else {
            CP_WAIT0();
        }
        __syncthreads();
        compute(smb + (uint32_t)(c & 1) * PBUF_B);
        __syncthreads();
    }

    GEMM_EPI_STAGE

#pragma unroll 4
    for (int ll = 0; ll < 64; ll++) {
        int flat = ll * 256 + tid;
        int n = flat & 127;
        int m = flat >> 7;
        out[(size_t)(m0 + m) * CC + n0 + n] = Ds[m * 132 + n] + bias[n0 + n];
    }
}

// ---------------------------------------------------------------------------
// Flash attention (unchanged from R13). S = single fp16 MMA; PV = pf*(vh+vl).
// BM=128 (8 warps x 16 rows), BN=64, 2 CTAs/SM, base-2 softmax, heavy-first.
// ---------------------------------------------------------------------------
#define AT_ROW 144
#define AT_TILE (64 * AT_ROW)              // 9216
#define AT_BUF (3 * AT_TILE)               // 27648
#define ATT_SMEM_BYTES (2 * AT_BUF)        // 55296
#define SCL2 0.1803368801111137f           // 0.125 * log2(e)

__global__ __launch_bounds__(256, 2) void attn_kernel() {
    extern __shared__ char smc[];
    const uint32_t smb = smem_u32(smc);
    const int tid = threadIdx.x;
    const int bh = blockIdx.y;
    const int q0 = (gridDim.x - 1 - blockIdx.x) * 128;   // heavy tiles first
    const int wid = tid >> 5;
    const int lane = tid & 31;
    const int gid = lane >> 2;
    const int tig = lane & 3;
    const int r0 = q0 + wid * 16 + gid;

    const __half* Qf = g_qf + (size_t)bh * TT * HD;
    const __half* Kf = g_kf + (size_t)bh * TT * HD;
    const __half* Vf = g_vf + (size_t)bh * HD * TT;
    const __half* Vl = g_vl + (size_t)bh * HD * TT;

    const uint32_t laneB = (uint32_t)(((lane & 7) + ((lane >> 4) & 1) * 8) * AT_ROW
                                      + ((lane >> 3) & 1) * 16);

    // ---- Q fragments (fp16, single), direct ldg
    uint32_t qf[4][4];
#pragma unroll
    for (int ks = 0; ks < 4; ks++)
#pragma unroll
        for (int hv = 0; hv < 2; hv++)
#pragma unroll
            for (int rr = 0; rr < 2; rr++) {
                size_t o = (size_t)(r0 + rr * 8) * HD + ks * 16 + hv * 8 + tig * 2;
                qf[ks][hv * 2 + rr] = *(const uint32_t*)(Qf + o);
            }

    float oacc[8][4];
#pragma unroll
    for (int j = 0; j < 8; j++)
#pragma unroll
        for (int q = 0; q < 4; q++) oacc[j][q] = 0.f;
    float mr0 = -1e30f, mr1 = -1e30f, lr0 = 0.f, lr1 = 0.f;

    auto copyc = [&](int c, int bufi) {
        const int k0 = c * 64;
        uint32_t bbase = smb + bufi * AT_BUF;
#pragma unroll
        for (int l = 0; l < 6; l++) {
            const int tile = l >> 1;            // 0=Kf, 1=Vf, 2=Vl
            int e2 = (l & 1) * 256 + tid;       // 0..511
            int r = e2 >> 3;                    // 0..63
            int q = e2 & 7;                     // 0..7
            const void* src;
            if (tile == 0)      src = Kf + (size_t)(k0 + r) * HD + q * 8;
            else if (tile == 1) src = Vf + (size_t)r * TT + k0 + q * 8;
            else                src = Vl + (size_t)r * TT + k0 + q * 8;
            cpa16(bbase + tile * AT_TILE + r * AT_ROW + q * 16, src);
        }
    };

    const int jmax = (q0 >> 6) + 2;
    copyc(0, 0);
    CP_COMMIT();
    for (int c = 0; c < jmax; c++) {
        if (c + 1 < jmax) {
            copyc(c + 1, (c + 1) & 1);
            CP_COMMIT();
            CP_WAIT1();
        } else {
            CP_WAIT0();
        }
        __syncthreads();
        const uint32_t KT = smb + (uint32_t)(c & 1) * AT_BUF;
        const uint32_t VT = KT + AT_TILE;

        // ---- S = Q K^T, single fp16 product
        float s[8][4];
#pragma unroll
        for (int j = 0; j < 8; j++)
#pragma unroll
            for (int q = 0; q < 4; q++) s[j][q] = 0.f;
#pragma unroll
        for (int ks = 0; ks < 4; ks++) {
#pragma unroll
            for (int jp = 0; jp < 4; jp++) {
                uint32_t kaddr = KT + laneB + jp * 16 * AT_ROW + ks * 32;
                uint32_t rk[4];
                LDSM4(rk, kaddr);
#pragma unroll
                for (int t = 0; t < 2; t++) {
                    int j = 2 * jp + t;
                    mma16816h(s[j], qf[ks], rk[2 * t], rk[2 * t + 1]);
                }
            }
        }

        // scale into base-2 logit domain
        const int k0 = c * 64;
#pragma unroll
        for (int j = 0; j < 8; j++)
#pragma unroll
            for (int q = 0; q < 4; q++) s[j][q] *= SCL2;
        if (c >= jmax - 2) {
#pragma unroll
            for (int j = 0; j < 8; j++) {
                int col = k0 + 8 * j + 2 * tig;
                if (col > r0)          s[j][0] = -1e30f;
                if (col + 1 > r0)      s[j][1] = -1e30f;
                if (col > r0 + 8)      s[j][2] = -1e30f;
                if (col + 1 > r0 + 8)  s[j][3] = -1e30f;
            }
        }

        // ---- online softmax (base-2)
        float pm0 = -1e30f, pm1 = -1e30f;
#pragma unroll
        for (int j = 0; j < 8; j++) {
            pm0 = fmaxf(pm0, fmaxf(s[j][0], s[j][1]));
            pm1 = fmaxf(pm1, fmaxf(s[j][2], s[j][3]));
        }
        pm0 = fmaxf(pm0, __shfl_xor_sync(0xffffffffu, pm0, 1));
        pm0 = fmaxf(pm0, __shfl_xor_sync(0xffffffffu, pm0, 2));
        pm1 = fmaxf(pm1, __shfl_xor_sync(0xffffffffu, pm1, 1));
        pm1 = fmaxf(pm1, __shfl_xor_sync(0xffffffffu, pm1, 2));
        float mn0 = fmaxf(mr0, pm0), mn1 = fmaxf(mr1, pm1);
        float a0 = ex2f(mr0 - mn0), a1 = ex2f(mr1 - mn1);
        float sum0 = 0.f, sum1 = 0.f;
#pragma unroll
        for (int j = 0; j < 8; j++) {
            s[j][0] = ex2f(s[j][0] - mn0);
            s[j][1] = ex2f(s[j][1] - mn0);
            s[j][2] = ex2f(s[j][2] - mn1);
            s[j][3] = ex2f(s[j][3] - mn1);
            sum0 += s[j][0] + s[j][1];
            sum1 += s[j][2] + s[j][3];
        }
        sum0 += __shfl_xor_sync(0xffffffffu, sum0, 1);
        sum0 += __shfl_xor_sync(0xffffffffu, sum0, 2);
        sum1 += __shfl_xor_sync(0xffffffffu, sum1, 1);
        sum1 += __shfl_xor_sync(0xffffffffu, sum1, 2);
        lr0 = lr0 * a0 + sum0;
        lr1 = lr1 * a1 + sum1;
        mr0 = mn0; mr1 = mn1;
#pragma unroll
        for (int j = 0; j < 8; j++) {
            oacc[j][0] *= a0; oacc[j][1] *= a0;
            oacc[j][2] *= a1; oacc[j][3] *= a1;
        }

        // ---- O += P V (pf * vh + pf * vl), P single fp16, packed per-ks
#pragma unroll
        for (int ks = 0; ks < 4; ks++) {
            uint32_t pf[4];
            int j0 = 2 * ks, j1 = 2 * ks + 1;
#pragma unroll
            for (int part = 0; part < 4; part++) {
                int jj = (part < 2) ? j0 : j1;
                int qa = (part & 1) * 2;
                pf[part] = h2u(__floats2half2_rn(s[jj][qa], s[jj][qa + 1]));
            }
#pragma unroll
            for (int jp = 0; jp < 4; jp++) {
                uint32_t vaddr = VT + laneB + jp * 16 * AT_ROW + ks * 32;
                uint32_t rh[4], rl[4];
                LDSM4(rh, vaddr);
                LDSM4(rl, vaddr + AT_TILE);
#pragma unroll
                for (int t = 0; t < 2; t++) {
                    int j = 2 * jp + t;
                    mma16816h(oacc[j], pf, rh[2 * t], rh[2 * t + 1]);
                    mma16816h(oacc[j], pf, rl[2 * t], rl[2 * t + 1]);
                }
            }
        }
        __syncthreads();
    }

    // ---- epilogue: normalize, write g_af (fp16 single) [B,T,C]
    const int b = bh >> 4;
    const int h = bh & 15;
    float inv0 = 1.f / lr0, inv1 = 1.f / lr1;
#pragma unroll
    for (int j = 0; j < 8; j++) {
        int d = 8 * j + 2 * tig;
        size_t o0 = ((size_t)(b * TT + r0)) * CC + h * HD + d;
        size_t o1 = ((size_t)(b * TT + r0 + 8)) * CC + h * HD + d;
        *(uint32_t*)(g_af + o0) =
            h2u(__floats2half2_rn(oacc[j][0] * inv0, oacc[j][1] * inv0));
        *(uint32_t*)(g_af + o1) =
            h2u(__floats2half2_rn(oacc[j][2] * inv1, oacc[j][3] * inv1));
    }
}

// ---------------------------------------------------------------------------

extern "C" void kernel_launch(void* const* d_in, const int* in_sizes, int n_in,
                              void* d_out, int out_size) {
    const float* x      = (const float*)d_in[0];
    const float* w_qkv  = (const float*)d_in[1];
    const float* w_proj = (const float*)d_in[2];
    const float* b_proj = (const float*)d_in[3];
    float* out = (float*)d_out;

    __half *xf, *wqf, *wpf, *wpl, *af;
    cudaGetSymbolAddress((void**)&xf,  g_xf);
    cudaGetSymbolAddress((void**)&wqf, g_wqf);
    cudaGetSymbolAddress((void**)&wpf, g_wpf);
    cudaGetSymbolAddress((void**)&wpl, g_wpl);
    cudaGetSymbolAddress((void**)&af,  g_af);

    cudaFuncSetAttribute(qkv_gemm, cudaFuncAttributeMaxDynamicSharedMemorySize, GSMEM);
    cudaFuncSetAttribute(proj_gemm, cudaFuncAttributeMaxDynamicSharedMemorySize, GSMEM);
    cudaFuncSetAttribute(attn_kernel, cudaFuncAttributeMaxDynamicSharedMemorySize, ATT_SMEM_BYTES);

    tofp16_kernel<<<2048, 256>>>(x, xf, MROWS * CC / 4);
    tofp16_kernel<<<2048, 256>>>(w_qkv, wqf, N_QKV * CC / 4);
    split_kernel_h<<<1024, 256>>>(w_proj, wpf, wpl, CC * CC / 4);

    qkv_gemm<<<dim3(N_QKV / 128, MROWS / 128), 256, GSMEM>>>(xf, wqf);
    attn_kernel<<<dim3(TT / 128, BB * HH), 256, ATT_SMEM_BYTES>>>();
    proj_gemm<<<dim3(CC / 128, MROWS / 128), 256, GSMEM>>>(af, wpf, wpl, b_proj, out);
}

// round 17
// speedup vs baseline: 1.3772x; 1.1130x over previous
#include <cuda_runtime.h>
#include <cuda_bf16.h>
#include <cuda_fp16.h>
#include <math.h>
#include <stdint.h>

// Problem constants
#define BB 4
#define TT 2048
#define CC 1024
#define HH 16
#define HD 64
#define MROWS (BB * TT)          // 8192
#define N_QKV (3 * CC)           // 3072

// ---------------------------------------------------------------------------
// Global scratch (allocation-free)
// ---------------------------------------------------------------------------
__device__ __half g_xf[MROWS * CC];                                  // x fp16 single
__device__ __half g_wqf[N_QKV * CC];                                 // w_qkv fp16 single
__device__ __half g_wpf[CC * CC],    g_wpl[CC * CC];                 // w_proj fp16 hi/lo
__device__ __half g_qf[BB * HH * TT * HD];                           // [bh][t][d] fp16
__device__ __half g_kf[BB * HH * TT * HD];                           // [bh][t][d] fp16
__device__ __half g_vf[BB * HH * TT * HD];                           // [bh][d][t] fp16 single
__device__ __half g_af[MROWS * CC];                                  // att out [B,T,C] fp16

// ---------------------------------------------------------------------------
// Helpers
// ---------------------------------------------------------------------------
__device__ __forceinline__ uint32_t h2u(__half2 h) {
    return *reinterpret_cast<uint32_t*>(&h);
}
__device__ __forceinline__ uint32_t smem_u32(const void* p) {
    uint32_t a;
    asm("{ .reg .u64 t; cvta.to.shared.u64 t, %1; cvt.u32.u64 %0, t; }"
        : "=r"(a) : "l"(p));
    return a;
}
__device__ __forceinline__ void cpa16(uint32_t dst, const void* src) {
    asm volatile("cp.async.cg.shared.global [%0], [%1], 16;"
                 :: "r"(dst), "l"(src) : "memory");
}
#define CP_COMMIT() asm volatile("cp.async.commit_group;" ::: "memory")
#define CP_WAIT0()  asm volatile("cp.async.wait_group 0;" ::: "memory")
#define CP_WAIT1()  asm volatile("cp.async.wait_group 1;" ::: "memory")

#define LDSM4(r, addr) \
    asm volatile("ldmatrix.sync.aligned.m8n8.x4.shared.b16 {%0,%1,%2,%3}, [%4];" \
        : "=r"((r)[0]), "=r"((r)[1]), "=r"((r)[2]), "=r"((r)[3]) : "r"(addr))

__device__ __forceinline__ float ex2f(float x) {
    float r;
    asm("ex2.approx.f32 %0, %1;" : "=f"(r) : "f"(x));
    return r;
}

__device__ __forceinline__ void mma16816h(float* c, const uint32_t* a,
                                          uint32_t b0, uint32_t b1) {
    asm volatile(
        "mma.sync.aligned.m16n8k16.row.col.f32.f16.f16.f32 "
        "{%0,%1,%2,%3}, {%4,%5,%6,%7}, {%8,%9}, {%0,%1,%2,%3};"
        : "+f"(c[0]), "+f"(c[1]), "+f"(c[2]), "+f"(c[3])
        : "r"(a[0]), "r"(a[1]), "r"(a[2]), "r"(a[3]), "r"(b0), "r"(b1));
}

// ---------------------------------------------------------------------------
// Elementwise pre-passes
// ---------------------------------------------------------------------------
__global__ void tofp16_kernel(const float* __restrict__ src,
                              __half* __restrict__ d, int n4) {
    int i = blockIdx.x * blockDim.x + threadIdx.x;
    int stride = gridDim.x * blockDim.x;
    for (; i < n4; i += stride) {
        float4 v = ((const float4*)src)[i];
        ((uint2*)d)[i] = make_uint2(h2u(__floats2half2_rn(v.x, v.y)),
                                    h2u(__floats2half2_rn(v.z, v.w)));
    }
}

__global__ void split_kernel_h(const float* __restrict__ src,
                               __half* __restrict__ dh,
                               __half* __restrict__ dl, int n4) {
    int i = blockIdx.x * blockDim.x + threadIdx.x;
    int stride = gridDim.x * blockDim.x;
    for (; i < n4; i += stride) {
        float4 v = ((const float4*)src)[i];
        __half2 h01 = __floats2half2_rn(v.x, v.y);
        __half2 h23 = __floats2half2_rn(v.z, v.w);
        float2 f01 = __half22float2(h01);
        float2 f23 = __half22float2(h23);
        __half2 l01 = __floats2half2_rn(v.x - f01.x, v.y - f01.y);
        __half2 l23 = __floats2half2_rn(v.z - f23.x, v.w - f23.y);
        ((uint2*)dh)[i] = make_uint2(h2u(h01), h2u(h23));
        ((uint2*)dl)[i] = make_uint2(h2u(l01), h2u(l23));
    }
}

// ---------------------------------------------------------------------------
// Common GEMM geometry: 128x128 tile, K-chunk 32, 8 warps 4x2,
// smem rows padded to 80B (LDSM conflict-free), cp.async double-buffer,
// 2 CTAs/SM (verified pipeline: 2 stages, 2 barriers/chunk).
// ---------------------------------------------------------------------------
#define APAD_B 80
#define TILE_B (128 * APAD_B)              // 10240
#define QBUF_B (2 * TILE_B)                // AF, WF = 20480 (qkv, 1 product)
#define PBUF_B (3 * TILE_B)                // AF, WH, WL = 30720 (proj, 2 products)
#define GSMEM  (128 * 132 * 4)             // 67584: covers both pipelines + Ds
#define NCHUNK (CC / 32)                   // 32

#define GEMM_PREAMBLE                                                          \
    const uint32_t smb = smem_u32(smc);                                        \
    const int tid = threadIdx.x;                                               \
    const int m0 = blockIdx.y * 128;                                           \
    const int n0 = blockIdx.x * 128;                                           \
    const int wid = tid >> 5;                                                  \
    const int lane = tid & 31;                                                 \
    const int gid = lane >> 2;                                                 \
    const int tig = lane & 3;                                                  \
    const int wm = wid & 3;                                                    \
    const int wn = wid >> 2;                                                   \
    const uint32_t laneA = (uint32_t)(((lane & 7) + ((lane >> 3) & 1) * 8)     \
                                      * APAD_B + (lane >> 4) * 16);            \
    const uint32_t laneB = (uint32_t)(((lane & 7) + ((lane >> 4) & 1) * 8)     \
                                      * APAD_B + ((lane >> 3) & 1) * 16);      \
    float acc[2][8][4];                                                        \
    _Pragma("unroll")                                                          \
    for (int i = 0; i < 2; i++)                                                \
        _Pragma("unroll")                                                      \
        for (int j = 0; j < 8; j++)                                            \
            _Pragma("unroll")                                                  \
            for (int q = 0; q < 4; q++) acc[i][j][q] = 0.f;

#define GEMM_EPI_STAGE                                                         \
    float* Ds = (float*)smc;                                                   \
    _Pragma("unroll")                                                          \
    for (int i = 0; i < 2; i++) {                                              \
        int rr = wm * 32 + i * 16 + gid;                                       \
        _Pragma("unroll")                                                      \
        for (int j = 0; j < 8; j++) {                                          \
            int cc = wn * 64 + j * 8 + tig * 2;                                \
            *(float2*)&Ds[rr * 132 + cc] =                                     \
                make_float2(acc[i][j][0], acc[i][j][1]);                       \
            *(float2*)&Ds[(rr + 8) * 132 + cc] =                               \
                make_float2(acc[i][j][2], acc[i][j][3]);                       \
        }                                                                      \
    }                                                                          \
    __syncthreads();

// ---------------------------------------------------------------------------
// QKV GEMM: single fp16 product (A fp16, W fp16). Epilogue writes
// Q/K fp16 + V fp16 single transposed.
// ---------------------------------------------------------------------------
__global__ __launch_bounds__(256, 2) void qkv_gemm(
    const __half* __restrict__ AF, const __half* __restrict__ WF) {
    extern __shared__ char smc[];
    GEMM_PREAMBLE

    auto copyc = [&](int kk, int bufi) {
        uint32_t bbase = smb + bufi * QBUF_B;
#pragma unroll
        for (int l = 0; l < 4; l++) {
            const int tile = l >> 1;               // 0=AF, 1=WF
            int e2 = (l & 1) * 256 + tid;          // 0..511
            int r = e2 >> 2;
            int q = e2 & 3;
            const __half* src = (tile == 0) ? AF : WF;
            int row = (tile == 0 ? m0 : n0) + r;
            cpa16(bbase + tile * TILE_B + r * APAD_B + q * 16,
                  src + (size_t)row * CC + kk + q * 8);
        }
    };

    auto compute = [&](uint32_t bufu) {
#pragma unroll
        for (int ks = 0; ks < 2; ks++) {
            uint32_t af[2][4];
#pragma unroll
            for (int i = 0; i < 2; i++) {
                uint32_t aaddr = bufu + laneA + (wm * 32 + i * 16) * APAD_B + ks * 32;
                LDSM4(af[i], aaddr);
            }
#pragma unroll
            for (int jp = 0; jp < 4; jp++) {
                uint32_t baddr = bufu + TILE_B + laneB
                               + (wn * 64 + jp * 16) * APAD_B + ks * 32;
                uint32_t rf[4];
                LDSM4(rf, baddr);
#pragma unroll
                for (int t = 0; t < 2; t++) {
                    int j = 2 * jp + t;
#pragma unroll
                    for (int i = 0; i < 2; i++)
                        mma16816h(acc[i][j], af[i], rf[2 * t], rf[2 * t + 1]);
                }
            }
        }
    };

    copyc(0, 0);
    CP_COMMIT();
    for (int c = 0; c < NCHUNK; c++) {
        if (c + 1 < NCHUNK) {
            copyc((c + 1) * 32, (c + 1) & 1);
            CP_COMMIT();
            CP_WAIT1();
        } else {
            CP_WAIT0();
        }
        __syncthreads();
        compute(smb + (uint32_t)(c & 1) * QBUF_B);
        __syncthreads();
    }

    GEMM_EPI_STAGE

    // two 64-wide segments; each wholly one of q/k/v (192 % 64 == 0)
#pragma unroll
    for (int seg = 0; seg < 2; seg++) {
        int gn0 = n0 + seg * 64;
        int h = gn0 / 192;
        int part = (gn0 % 192) >> 6;
        if (part < 2) {
            __half* dst = (part == 0) ? g_qf : g_kf;       // fp16, single
#pragma unroll
            for (int it = 0; it < 16; it++) {
                int m = it * 8 + (tid >> 5);
                int d2 = (tid & 31) * 2;
                float v0 = Ds[m * 132 + seg * 64 + d2];
                float v1 = Ds[m * 132 + seg * 64 + d2 + 1];
                __half2 hp = __floats2half2_rn(v0, v1);
                int gm = m0 + m; int b = gm >> 11; int t = gm & 2047;
                size_t idx = (((size_t)(b * HH + h)) * TT + t) * HD + d2;
                *(uint32_t*)(dst + idx) = h2u(hp);
            }
        } else {                            // V: transposed [bh][d][t], fp16 single
#pragma unroll
            for (int it = 0; it < 16; it++) {
                int flat = it * 256 + tid;         // 0..4095
                int d = flat >> 6;                 // 0..63
                int tp = (flat & 63) * 2;          // pair along t
                float v0 = Ds[tp * 132 + seg * 64 + d];
                float v1 = Ds[(tp + 1) * 132 + seg * 64 + d];
                __half2 hp = __floats2half2_rn(v0, v1);
                int gm = m0 + tp; int b = gm >> 11; int t = gm & 2047;
                size_t idx = (((size_t)(b * HH + h)) * HD + d) * TT + t;
                *(uint32_t*)(g_vf + idx) = h2u(hp);
            }
        }
    }
}

// ---------------------------------------------------------------------------
// Proj GEMM: 2 fp16 products (A fp16 single, W fp16 hi/lo). out = C + bias.
// ---------------------------------------------------------------------------
__global__ __launch_bounds__(256, 2) void proj_gemm(
    const __half* __restrict__ AF,
    const __half* __restrict__ WH, const __half* __restrict__ WL,
    const float* __restrict__ bias, float* __restrict__ out) {
    extern __shared__ char smc[];
    GEMM_PREAMBLE

    auto copyc = [&](int kk, int bufi) {
        uint32_t bbase = smb + bufi * PBUF_B;
#pragma unroll
        for (int l = 0; l < 6; l++) {
            const int tile = l >> 1;               // 0=AF, 1=WH, 2=WL
            int e2 = (l & 1) * 256 + tid;
            int r = e2 >> 2;
            int q = e2 & 3;
            const __half* src = (tile == 0) ? AF : (tile == 1) ? WH : WL;
            int row = (tile == 0 ? m0 : n0) + r;
            cpa16(bbase + tile * TILE_B + r * APAD_B + q * 16,
                  src + (size_t)row * CC + kk + q * 8);
        }
    };

    auto compute = [&](uint32_t bufu) {
#pragma unroll
        for (int ks = 0; ks < 2; ks++) {
            uint32_t af[2][4];
#pragma unroll
            for (int i = 0; i < 2; i++) {
                uint32_t aaddr = bufu + laneA + (wm * 32 + i * 16) * APAD_B + ks * 32;
                LDSM4(af[i], aaddr);
            }
#pragma unroll
            for (int jp = 0; jp < 4; jp++) {
                uint32_t baddr = bufu + TILE_B + laneB
                               + (wn * 64 + jp * 16) * APAD_B + ks * 32;
                uint32_t rh[4], rl[4];
                LDSM4(rh, baddr);
                LDSM4(rl, baddr + TILE_B);
#pragma unroll
                for (int t = 0; t < 2; t++) {
                    int j = 2 * jp + t;
#pragma unroll
                    for (int i = 0; i < 2; i++) {
                        mma16816h(acc[i][j], af[i], rh[2 * t], rh[2 * t + 1]);
                        mma16816h(acc[i][j], af[i], rl[2 * t], rl[2 * t + 1]);
                    }
                }
            }
        }
    };

    copyc(0, 0);
    CP_COMMIT();
    for (int c = 0; c < NCHUNK; c++) {
        if (c + 1 < NCHUNK) {
            copyc((c + 1) * 32, (c + 1) & 1);
            CP_COMMIT();
            CP_WAIT1();
        } else {
            CP_WAIT0();
        }
        __syncthreads();
        compute(smb + (uint32_t)(c & 1) * PBUF_B);
        __syncthreads();
    }

    GEMM_EPI_STAGE

#pragma unroll 4
    for (int ll = 0; ll < 64; ll++) {
        int flat = ll * 256 + tid;
        int n = flat & 127;
        int m = flat >> 7;
        out[(size_t)(m0 + m) * CC + n0 + n] = Ds[m * 132 + n] + bias[n0 + n];
    }
}

// ---------------------------------------------------------------------------
// Flash attention. S = Q K^T single fp16 MMA; PV = single fp16 MMA (V fp16).
// BM=128 (8 warps x 16 rows), BN=64, 2 CTAs/SM, base-2 softmax, heavy-first.
// Smem per buffer: Kf + Vf (fp16), rows padded to 144B.
// ---------------------------------------------------------------------------
#define AT_ROW 144
#define AT_TILE (64 * AT_ROW)              // 9216
#define AT_BUF (2 * AT_TILE)               // Kf, Vf = 18432
#define ATT_SMEM_BYTES (2 * AT_BUF)        // 36864
#define SCL2 0.1803368801111137f           // 0.125 * log2(e)

__global__ __launch_bounds__(256, 2) void attn_kernel() {
    extern __shared__ char smc[];
    const uint32_t smb = smem_u32(smc);
    const int tid = threadIdx.x;
    const int bh = blockIdx.y;
    const int q0 = (gridDim.x - 1 - blockIdx.x) * 128;   // heavy tiles first
    const int wid = tid >> 5;
    const int lane = tid & 31;
    const int gid = lane >> 2;
    const int tig = lane & 3;
    const int r0 = q0 + wid * 16 + gid;

    const __half* Qf = g_qf + (size_t)bh * TT * HD;
    const __half* Kf = g_kf + (size_t)bh * TT * HD;
    const __half* Vf = g_vf + (size_t)bh * HD * TT;

    const uint32_t laneB = (uint32_t)(((lane & 7) + ((lane >> 4) & 1) * 8) * AT_ROW
                                      + ((lane >> 3) & 1) * 16);

    // ---- Q fragments (fp16, single), direct ldg
    uint32_t qf[4][4];
#pragma unroll
    for (int ks = 0; ks < 4; ks++)
#pragma unroll
        for (int hv = 0; hv < 2; hv++)
#pragma unroll
            for (int rr = 0; rr < 2; rr++) {
                size_t o = (size_t)(r0 + rr * 8) * HD + ks * 16 + hv * 8 + tig * 2;
                qf[ks][hv * 2 + rr] = *(const uint32_t*)(Qf + o);
            }

    float oacc[8][4];
#pragma unroll
    for (int j = 0; j < 8; j++)
#pragma unroll
        for (int q = 0; q < 4; q++) oacc[j][q] = 0.f;
    float mr0 = -1e30f, mr1 = -1e30f, lr0 = 0.f, lr1 = 0.f;

    auto copyc = [&](int c, int bufi) {
        const int k0 = c * 64;
        uint32_t bbase = smb + bufi * AT_BUF;
#pragma unroll
        for (int l = 0; l < 4; l++) {
            const int tile = l >> 1;            // 0=Kf, 1=Vf
            int e2 = (l & 1) * 256 + tid;       // 0..511
            int r = e2 >> 3;                    // 0..63
            int q = e2 & 7;                     // 0..7
            const void* src;
            if (tile == 0) src = Kf + (size_t)(k0 + r) * HD + q * 8;
            else           src = Vf + (size_t)r * TT + k0 + q * 8;
            cpa16(bbase + tile * AT_TILE + r * AT_ROW + q * 16, src);
        }
    };

    const int jmax = (q0 >> 6) + 2;
    copyc(0, 0);
    CP_COMMIT();
    for (int c = 0; c < jmax; c++) {
        if (c + 1 < jmax) {
            copyc(c + 1, (c + 1) & 1);
            CP_COMMIT();
            CP_WAIT1();
        } else {
            CP_WAIT0();
        }
        __syncthreads();
        const uint32_t KT = smb + (uint32_t)(c & 1) * AT_BUF;
        const uint32_t VT = KT + AT_TILE;

        // ---- S = Q K^T, single fp16 product
        float s[8][4];
#pragma unroll
        for (int j = 0; j < 8; j++)
#pragma unroll
            for (int q = 0; q < 4; q++) s[j][q] = 0.f;
#pragma unroll
        for (int ks = 0; ks < 4; ks++) {
#pragma unroll
            for (int jp = 0; jp < 4; jp++) {
                uint32_t kaddr = KT + laneB + jp * 16 * AT_ROW + ks * 32;
                uint32_t rk[4];
                LDSM4(rk, kaddr);
#pragma unroll
                for (int t = 0; t < 2; t++) {
                    int j = 2 * jp + t;
                    mma16816h(s[j], qf[ks], rk[2 * t], rk[2 * t + 1]);
                }
            }
        }

        // scale into base-2 logit domain
        const int k0 = c * 64;
#pragma unroll
        for (int j = 0; j < 8; j++)
#pragma unroll
            for (int q = 0; q < 4; q++) s[j][q] *= SCL2;
        if (c >= jmax - 2) {
#pragma unroll
            for (int j = 0; j < 8; j++) {
                int col = k0 + 8 * j + 2 * tig;
                if (col > r0)          s[j][0] = -1e30f;
                if (col + 1 > r0)      s[j][1] = -1e30f;
                if (col > r0 + 8)      s[j][2] = -1e30f;
                if (col + 1 > r0 + 8)  s[j][3] = -1e30f;
            }
        }

        // ---- online softmax (base-2)
        float pm0 = -1e30f, pm1 = -1e30f;
#pragma unroll
        for (int j = 0; j < 8; j++) {
            pm0 = fmaxf(pm0, fmaxf(s[j][0], s[j][1]));
            pm1 = fmaxf(pm1, fmaxf(s[j][2], s[j][3]));
        }
        pm0 = fmaxf(pm0, __shfl_xor_sync(0xffffffffu, pm0, 1));
        pm0 = fmaxf(pm0, __shfl_xor_sync(0xffffffffu, pm0, 2));
        pm1 = fmaxf(pm1, __shfl_xor_sync(0xffffffffu, pm1, 1));
        pm1 = fmaxf(pm1, __shfl_xor_sync(0xffffffffu, pm1, 2));
        float mn0 = fmaxf(mr0, pm0), mn1 = fmaxf(mr1, pm1);
        float a0 = ex2f(mr0 - mn0), a1 = ex2f(mr1 - mn1);
        float sum0 = 0.f, sum1 = 0.f;
#pragma unroll
        for (int j = 0; j < 8; j++) {
            s[j][0] = ex2f(s[j][0] - mn0);
            s[j][1] = ex2f(s[j][1] - mn0);
            s[j][2] = ex2f(s[j][2] - mn1);
            s[j][3] = ex2f(s[j][3] - mn1);
            sum0 += s[j][0] + s[j][1];
            sum1 += s[j][2] + s[j][3];
        }
        sum0 += __shfl_xor_sync(0xffffffffu, sum0, 1);
        sum0 += __shfl_xor_sync(0xffffffffu, sum0, 2);
        sum1 += __shfl_xor_sync(0xffffffffu, sum1, 1);
        sum1 += __shfl_xor_sync(0xffffffffu, sum1, 2);
        lr0 = lr0 * a0 + sum0;
        lr1 = lr1 * a1 + sum1;
        mr0 = mn0; mr1 = mn1;
#pragma unroll
        for (int j = 0; j < 8; j++) {
            oacc[j][0] *= a0; oacc[j][1] *= a0;
            oacc[j][2] *= a1; oacc[j][3] *= a1;
        }

        // ---- O += P V (single fp16 product), P packed per-ks
#pragma unroll
        for (int ks = 0; ks < 4; ks++) {
            uint32_t pf[4];
            int j0 = 2 * ks, j1 = 2 * ks + 1;
#pragma unroll
            for (int part = 0; part < 4; part++) {
                int jj = (part < 2) ? j0 : j1;
                int qa = (part & 1) * 2;
                pf[part] = h2u(__floats2half2_rn(s[jj][qa], s[jj][qa + 1]));
            }
#pragma unroll
            for (int jp = 0; jp < 4; jp++) {
                uint32_t vaddr = VT + laneB + jp * 16 * AT_ROW + ks * 32;
                uint32_t rv[4];
                LDSM4(rv, vaddr);
#pragma unroll
                for (int t = 0; t < 2; t++) {
                    int j = 2 * jp + t;
                    mma16816h(oacc[j], pf, rv[2 * t], rv[2 * t + 1]);
                }
            }
        }
        __syncthreads();
    }

    // ---- epilogue: normalize, write g_af (fp16 single) [B,T,C]
    const int b = bh >> 4;
    const int h = bh & 15;
    float inv0 = 1.f / lr0, inv1 = 1.f / lr1;
#pragma unroll
    for (int j = 0; j < 8; j++) {
        int d = 8 * j + 2 * tig;
        size_t o0 = ((size_t)(b * TT + r0)) * CC + h * HD + d;
        size_t o1 = ((size_t)(b * TT + r0 + 8)) * CC + h * HD + d;
        *(uint32_t*)(g_af + o0) =
            h2u(__floats2half2_rn(oacc[j][0] * inv0, oacc[j][1] * inv0));
        *(uint32_t*)(g_af + o1) =
            h2u(__floats2half2_rn(oacc[j][2] * inv1, oacc[j][3] * inv1));
    }
}

// ---------------------------------------------------------------------------

extern "C" void kernel_launch(void* const* d_in, const int* in_sizes, int n_in,
                              void* d_out, int out_size) {
    const float* x      = (const float*)d_in[0];
    const float* w_qkv  = (const float*)d_in[1];
    const float* w_proj = (const float*)d_in[2];
    const float* b_proj = (const float*)d_in[3];
    float* out = (float*)d_out;

    __half *xf, *wqf, *wpf, *wpl, *af;
    cudaGetSymbolAddress((void**)&xf,  g_xf);
    cudaGetSymbolAddress((void**)&wqf, g_wqf);
    cudaGetSymbolAddress((void**)&wpf, g_wpf);
    cudaGetSymbolAddress((void**)&wpl, g_wpl);
    cudaGetSymbolAddress((void**)&af,  g_af);

    cudaFuncSetAttribute(qkv_gemm, cudaFuncAttributeMaxDynamicSharedMemorySize, GSMEM);
    cudaFuncSetAttribute(proj_gemm, cudaFuncAttributeMaxDynamicSharedMemorySize, GSMEM);
    cudaFuncSetAttribute(attn_kernel, cudaFuncAttributeMaxDynamicSharedMemorySize, ATT_SMEM_BYTES);

    tofp16_kernel<<<2048, 256>>>(x, xf, MROWS * CC / 4);
    tofp16_kernel<<<2048, 256>>>(w_qkv, wqf, N_QKV * CC / 4);
    split_kernel_h<<<1024, 256>>>(w_proj, wpf, wpl, CC * CC / 4);

    qkv_gemm<<<dim3(N_QKV / 128, MROWS / 128), 256, GSMEM>>>(xf, wqf);
    attn_kernel<<<dim3(TT / 128, BB * HH), 256, ATT_SMEM_BYTES>>>();
    proj_gemm<<<dim3(CC / 128, MROWS / 128), 256, GSMEM>>>(af, wpf, wpl, b_proj, out);
}